// round 12
// baseline (speedup 1.0000x reference)
#include <cuda_runtime.h>
#include <cuda_bf16.h>
#include <math.h>
#include <stdint.h>

#define Bq 64
#define Tq 512
#define Iq 1024
#define Hq 1024
#define G4 4096          // 4*H
#define KEXP 3072        // 3 * Iq (phase-1 split, interleaved)
#define KR2 2048         // 2 * Hq (phase-2 split, segmented [ah|al])
#define NBLK 128

// ---- scratch (static __device__; no allocations allowed) ----
__device__ float g_xproj[(size_t)Tq * Bq * G4];               // [t][b][4H]
__device__ unsigned g_Aexp[(size_t)(Bq * Tq) * (KEXP / 2)];   // bf16x2 [m][k']
__device__ unsigned g_Bexp[(size_t)G4 * (KEXP / 2)];          // bf16x2 [n][k']
__device__ __align__(128) __nv_bfloat16 g_hexp[2][(size_t)KR2 * Bq]; // h' [k'][64]

__device__ unsigned g_bar_count = 0;
__device__ volatile unsigned g_bar_phase = 0;

// =============== helpers ===============
__device__ __forceinline__ uint32_t smem_u32(const void* p) {
    uint32_t a;
    asm("{ .reg .u64 t; cvta.to.shared.u64 t, %1; cvt.u32.u64 %0, t; }"
        : "=r"(a) : "l"(p));
    return a;
}

#define CP_ASYNC16(dst, src) \
    asm volatile("cp.async.cg.shared.global [%0], [%1], 16;" :: "r"(dst), "l"(src))
#define CP_COMMIT() asm volatile("cp.async.commit_group;" ::: "memory")
#define CP_WAIT0()  asm volatile("cp.async.wait_group 0;" ::: "memory")

#define LDMX4(r, addr) \
    asm volatile("ldmatrix.sync.aligned.m8n8.x4.shared.b16 {%0,%1,%2,%3}, [%4];" \
        : "=r"((r)[0]), "=r"((r)[1]), "=r"((r)[2]), "=r"((r)[3]) : "r"(addr))

#define LDMX4T(r, addr) \
    asm volatile("ldmatrix.sync.aligned.m8n8.x4.trans.shared.b16 {%0,%1,%2,%3}, [%4];" \
        : "=r"((r)[0]), "=r"((r)[1]), "=r"((r)[2]), "=r"((r)[3]) : "r"(addr))

#define MMA16816(c, a, b) \
    asm volatile("mma.sync.aligned.m16n8k16.row.col.f32.bf16.bf16.f32 " \
        "{%0,%1,%2,%3}, {%4,%5,%6,%7}, {%8,%9}, {%0,%1,%2,%3};" \
        : "+f"((c)[0]), "+f"((c)[1]), "+f"((c)[2]), "+f"((c)[3]) \
        : "r"((a)[0]), "r"((a)[1]), "r"((a)[2]), "r"((a)[3]), \
          "r"((b)[0]), "r"((b)[1]))

__device__ __forceinline__ void bf16_split(float v, unsigned& hi, unsigned& lo) {
    __nv_bfloat16 h = __float2bfloat16(v);
    float rem = v - __bfloat162float(h);
    __nv_bfloat16 l = __float2bfloat16(rem);
    hi = (unsigned)__bfloat16_as_ushort(h);
    lo = (unsigned)__bfloat16_as_ushort(l);
}

// =============== split / expand kernels (phase 1, unchanged) ===============
__global__ void split_x_kernel(const float* __restrict__ x) {
    size_t e2 = (size_t)blockIdx.x * 256 + threadIdx.x;
    float2 v = *(const float2*)(x + e2 * 2);
    size_t f0 = e2 * 2;
    size_t m = f0 >> 10;
    int k = (int)(f0 & 1023);
    unsigned h0, l0, h1, l1;
    bf16_split(v.x, h0, l0);
    bf16_split(v.y, h1, l1);
    unsigned* dst = g_Aexp + m * (KEXP / 2) + (size_t)(k >> 1) * 3;
    dst[0] = h0 | (h0 << 16);
    dst[1] = l0 | (h1 << 16);
    dst[2] = h1 | (l1 << 16);
}

__global__ void split_w_kernel(const float* __restrict__ Wx) {
    int n = blockIdx.x * 256 + threadIdx.x;
    unsigned* dst = g_Bexp + (size_t)n * (KEXP / 2);
#pragma unroll 4
    for (int k = 0; k < Iq; k += 2) {
        float w0 = Wx[(size_t)k * G4 + n];
        float w1 = Wx[(size_t)(k + 1) * G4 + n];
        unsigned h0, l0, h1, l1;
        bf16_split(w0, h0, l0);
        bf16_split(w1, h1, l1);
        unsigned* d = dst + (k >> 1) * 3;
        d[0] = h0 | (l0 << 16);
        d[1] = h0 | (h1 << 16);
        d[2] = l1 | (h1 << 16);
    }
}

// =============== Phase 1: mma.sync bf16 GEMM (unchanged from R5) ===============
__global__ void __launch_bounds__(256, 2)
gemm_xproj_mma(const float* __restrict__ bias) {
    __shared__ __align__(1024) unsigned char sm[2][16384];
    const uint32_t smbase = smem_u32(sm);

    const int tid  = threadIdx.x;
    const int wid  = tid >> 5;
    const int lane = tid & 31;
    const int wm   = wid & 1;
    const int wn   = wid >> 1;

    int bid = blockIdx.x;
    int gid = bid >> 9;
    int r = bid & 511;
    int mt = gid * 16 + (r & 15);
    int nt = r >> 4;
    const int m0 = mt * 128, n0 = nt * 128;

    const int gq = lane >> 3;
    const int rl = lane & 7;
    uint32_t a_addr[4], b_addr[2];
#pragma unroll
    for (int mf = 0; mf < 4; mf++) {
        int row = wm * 64 + mf * 16 + rl + (gq & 1) * 8;
        int q = (gq >> 1) ^ ((row >> 1) & 3);
        a_addr[mf] = smbase + row * 64 + q * 16;
    }
#pragma unroll
    for (int np = 0; np < 2; np++) {
        int row = wn * 32 + np * 16 + rl + (gq & 1) * 8;
        int q = (gq >> 1) ^ ((row >> 1) & 3);
        b_addr[np] = smbase + 8192 + row * 64 + q * 16;
    }

    const int4* A4 = (const int4*)g_Aexp;
    const int4* B4 = (const int4*)g_Bexp;
    auto load_chunk = [&](int c, int buf) {
        uint32_t sb = smbase + buf * 16384;
#pragma unroll
        for (int i = 0; i < 2; i++) {
            int u = tid + i * 256;
            int row = u >> 2, q = u & 3;
            uint32_t dst = sb + row * 64 + ((q ^ ((row >> 1) & 3)) << 4);
            CP_ASYNC16(dst, A4 + (size_t)(m0 + row) * 384 + c * 4 + q);
        }
#pragma unroll
        for (int i = 0; i < 2; i++) {
            int u = tid + i * 256;
            int row = u >> 2, q = u & 3;
            uint32_t dst = sb + 8192 + row * 64 + ((q ^ ((row >> 1) & 3)) << 4);
            CP_ASYNC16(dst, B4 + (size_t)(n0 + row) * 384 + c * 4 + q);
        }
    };

    float acc[4][4][4];
#pragma unroll
    for (int mf = 0; mf < 4; mf++)
#pragma unroll
        for (int nf = 0; nf < 4; nf++)
#pragma unroll
            for (int e = 0; e < 4; e++) acc[mf][nf][e] = 0.f;

    load_chunk(0, 0);
    CP_COMMIT();
    CP_WAIT0();
    __syncthreads();

    const int NCH = KEXP / 32;
    for (int c = 0; c < NCH; c++) {
        if (c + 1 < NCH) { load_chunk(c + 1, (c + 1) & 1); CP_COMMIT(); }

        const uint32_t boff = (c & 1) * 16384u;
#pragma unroll
        for (int kk = 0; kk < 2; kk++) {
            const uint32_t kx = kk << 5;
            uint32_t a[4][4], b[4][2];
#pragma unroll
            for (int mf = 0; mf < 4; mf++)
                LDMX4(a[mf], (a_addr[mf] + boff) ^ kx);
#pragma unroll
            for (int np = 0; np < 2; np++) {
                uint32_t rr[4];
                LDMX4(rr, (b_addr[np] + boff) ^ kx);
                b[np * 2][0] = rr[0]; b[np * 2][1] = rr[2];
                b[np * 2 + 1][0] = rr[1]; b[np * 2 + 1][1] = rr[3];
            }
#pragma unroll
            for (int mf = 0; mf < 4; mf++)
#pragma unroll
                for (int nf = 0; nf < 4; nf++)
                    MMA16816(acc[mf][nf], a[mf], b[nf]);
        }
        if (c + 1 < NCH) CP_WAIT0();
        __syncthreads();
    }

#pragma unroll
    for (int mf = 0; mf < 4; mf++) {
        int m = m0 + wm * 64 + mf * 16 + (lane >> 2);
#pragma unroll
        for (int nf = 0; nf < 4; nf++) {
            int n = n0 + wn * 32 + nf * 8 + (lane & 3) * 2;
            float2 bs = *(const float2*)&bias[n];
            {
                int b = m >> 9, t = m & 511;
                size_t idx = ((size_t)t * Bq + b) * G4 + n;
                float2 v = make_float2(acc[mf][nf][0] + bs.x, acc[mf][nf][1] + bs.y);
                *(float2*)&g_xproj[idx] = v;
            }
            {
                int m2 = m + 8;
                int b = m2 >> 9, t = m2 & 511;
                size_t idx = ((size_t)t * Bq + b) * G4 + n;
                float2 v = make_float2(acc[mf][nf][2] + bs.x, acc[mf][nf][3] + bs.y);
                *(float2*)&g_xproj[idx] = v;
            }
        }
    }
}

// =============== grid barrier ===============
__device__ __forceinline__ void grid_sync(unsigned expected) {
    __syncthreads();
    if (threadIdx.x == 0) {
        __threadfence();
        unsigned a = atomicAdd(&g_bar_count, 1u);
        if (a == (unsigned)(gridDim.x - 1)) {
            g_bar_count = 0;
            __threadfence();
            g_bar_phase = expected;
        } else {
            while (g_bar_phase != expected) __nanosleep(64);
        }
        __threadfence();
    }
    __syncthreads();
}

// =============== Phase 2: tensor-core persistent recurrence (v6) ===============
// Homogeneous 256 threads / 8 warps, phase-1-style loop: every warp both
// cp.asyncs the next chunk and MMAs the current one (2 MMA warps per SMSP).
// Warp w: m-strip ms = w&3 (batch rows ms*16..+15), n-half nh = w>>2
// (gate cols nh*16..+15). 8 chunks/step of 256 k'-rows (32KB), 2 buffers.
// Gate exchange for the pointwise via padded SMEM Ps[n][b] (stride 65).
// SMEM: BH @0 (64KB), BL @64KB, A bufs 2x32KB @128KB, Ps @192KB. ~200KB.
__global__ void __launch_bounds__(256, 1)
lstm_tc_kernel(const float* __restrict__ Wh, float* __restrict__ out) {
    extern __shared__ __align__(128) char sm2[];
    const uint32_t Bsb = smem_u32(sm2);
    const uint32_t Asb = Bsb + 131072u;
    float* Ps = (float*)(sm2 + 196608);   // [32 n][65] floats

    const int tid  = threadIdx.x;
    const int w    = tid >> 5;
    const int lane = tid & 31;
    const int j0   = blockIdx.x * 8;
    const int ms   = w & 3;               // m-strip (batch rows ms*16..+15)
    const int nh   = w >> 2;              // n-half (gate cols nh*16..+15)

    // ---- build split-Wh slices BH / BL (once) ----
    for (int idx = tid; idx < 32 * 1024; idx += 256) {
        int n = idx & 31;
        int k = idx >> 5;
        int g = n >> 3, jj = n & 7;
        float wv = Wh[(size_t)k * G4 + g * 1024 + j0 + jj];
        unsigned bh, bl;
        bf16_split(wv, bh, bl);
        uint32_t base = (uint32_t)(n * 2048 + (((k >> 3) ^ (n & 7)) << 4) + (k & 7) * 2);
        *(unsigned short*)(sm2 + base)          = (unsigned short)bh;
        *(unsigned short*)(sm2 + 65536u + base) = (unsigned short)bl;
    }

    // ---- zero my rows of h'[0] ----
    {
        __nv_bfloat16* hz = g_hexp[0];
        for (int idx = tid; idx < 16 * 64; idx += 256) {
            int r = idx >> 6;
            int row = (r < 8) ? (j0 + r) : (1024 + j0 + (r - 8));
            hz[(size_t)row * 64 + (idx & 63)] = __ushort_as_bfloat16(0);
        }
    }

    // ---- per-thread MMA constants ----
    const int gq = lane >> 3, rl = lane & 7;
    const uint32_t a_off = (uint32_t)((rl + ((gq >> 1) << 3)) * 128 +
                           ((ms * 32 + (gq & 1) * 16) ^ (rl << 4)));
    const uint32_t b_row = (uint32_t)((nh * 16 + rl + (gq & 1) * 8) * 2048);
    const uint32_t gqk = (uint32_t)(gq >> 1);
    const uint32_t bswz = (uint32_t)rl;

    float acc[2][4];
#pragma unroll
    for (int f = 0; f < 2; f++)
#pragma unroll
        for (int e = 0; e < 4; e++) acc[f][e] = 0.f;
    float cst[2] = {0.f, 0.f};

    unsigned phase0 = 0;
    if (tid == 0) phase0 = g_bar_phase;
    unsigned nbar = 0;
    nbar++; grid_sync(phase0 + nbar);     // BH/BL + h'[0] visible

    // xproj prefetch regs: combos c0 = tid, c1 = tid + 256 -> (b, jj)
    const int b0 = tid >> 3, jj0 = tid & 7;           // combo 0
    const int b1 = (tid + 256) >> 3, jj1 = tid & 7;   // combo 1 (b0 + 32)
    float xp[2][4];
#pragma unroll
    for (int g = 0; g < 4; g++) {
        xp[0][g] = g_xproj[(size_t)b0 * G4 + j0 + jj0 + g * 1024];
        xp[1][g] = g_xproj[(size_t)b1 * G4 + j0 + jj1 + g * 1024];
    }

    // chunk loader: 32KB = 2048 16B lines, 8 per thread
    auto load_chunk = [&](const __nv_bfloat16* Asrc, int ch, uint32_t buf) {
        uint32_t sbuf = Asb + buf * 32768u;
        const __nv_bfloat16* src = Asrc + (size_t)ch * 16384;
#pragma unroll
        for (int i = 0; i < 8; i++) {
            int u = tid + i * 256;
            int krow = u >> 3, q = u & 7;
            uint32_t dst = sbuf + krow * 128 + (((uint32_t)q ^ (krow & 7)) << 4);
            CP_ASYNC16(dst, src + (size_t)krow * 64 + q * 8);
        }
        CP_COMMIT();
    };

    for (int t = 0; t < Tq; t++) {
        const __nv_bfloat16* Asrc = g_hexp[t & 1];

        load_chunk(Asrc, 0, 0);
        CP_WAIT0();
        __syncthreads();

        for (int ch = 0; ch < 8; ch++) {
            if (ch + 1 < 8) load_chunk(Asrc, ch + 1, (ch + 1) & 1);

            const uint32_t abase = Asb + (uint32_t)(ch & 1) * 32768u + a_off;
            const uint32_t kc0 = (uint32_t)((ch & 3) * 32);
            if (ch < 4) {
                // ah chunk: vs BH and BL
#pragma unroll
                for (int kk = 0; kk < 16; kk++) {
                    uint32_t a[4];
                    LDMX4T(a, abase + kk * 2048);
                    uint32_t cidx = ((kc0 + kk * 2) | gqk) ^ bswz;
                    uint32_t rr[4];
                    LDMX4(rr, Bsb + b_row + (cidx << 4));
                    uint32_t bh0[2] = {rr[0], rr[2]};
                    uint32_t bh1[2] = {rr[1], rr[3]};
                    LDMX4(rr, Bsb + 65536u + b_row + (cidx << 4));
                    uint32_t bl0[2] = {rr[0], rr[2]};
                    uint32_t bl1[2] = {rr[1], rr[3]};
                    MMA16816(acc[0], a, bh0);
                    MMA16816(acc[1], a, bh1);
                    MMA16816(acc[0], a, bl0);
                    MMA16816(acc[1], a, bl1);
                }
            } else {
                // al chunk: vs BH only
#pragma unroll
                for (int kk = 0; kk < 16; kk++) {
                    uint32_t a[4];
                    LDMX4T(a, abase + kk * 2048);
                    uint32_t cidx = ((kc0 + kk * 2) | gqk) ^ bswz;
                    uint32_t rr[4];
                    LDMX4(rr, Bsb + b_row + (cidx << 4));
                    uint32_t bh0[2] = {rr[0], rr[2]};
                    uint32_t bh1[2] = {rr[1], rr[3]};
                    MMA16816(acc[0], a, bh0);
                    MMA16816(acc[1], a, bh1);
                }
            }
            if (ch + 1 < 8) CP_WAIT0();
            __syncthreads();
        }

        // ---- publish accumulators to Ps[n][b] (stride 65) ----
#pragma unroll
        for (int f = 0; f < 2; f++)
#pragma unroll
            for (int e = 0; e < 4; e++) {
                int bb = ms * 16 + (lane >> 2) + ((e >> 1) << 3);
                int nn = nh * 16 + f * 8 + (lane & 3) * 2 + (e & 1);
                Ps[nn * 65 + bb] = acc[f][e];
                acc[f][e] = 0.f;
            }
        __syncthreads();

        // ---- pointwise: 2 (b, jj) combos per thread ----
        __nv_bfloat16* hn = g_hexp[(t + 1) & 1];
#pragma unroll
        for (int ci = 0; ci < 2; ci++) {
            int bb = ci ? b1 : b0;
            int jj = ci ? jj1 : jj0;
            float ig = Ps[(0 * 8 + jj) * 65 + bb] + xp[ci][0];
            float fg = Ps[(1 * 8 + jj) * 65 + bb] + xp[ci][1];
            float gg = Ps[(2 * 8 + jj) * 65 + bb] + xp[ci][2];
            float og = Ps[(3 * 8 + jj) * 65 + bb] + xp[ci][3];

            float iv = 1.f / (1.f + __expf(-ig));
            float fv = 1.f / (1.f + __expf(-fg));
            float gv = tanhf(gg);
            float ov = 1.f / (1.f + __expf(-og));

            float c = fv * cst[ci] + iv * gv;
            float h = ov * tanhf(c);
            cst[ci] = c;

            out[((size_t)bb * Tq + t) * Hq + j0 + jj] = h;

            __nv_bfloat16 ah = __float2bfloat16(h);
            float rem = h - __bfloat162float(ah);
            __nv_bfloat16 al = __float2bfloat16(rem);
            hn[(size_t)(j0 + jj) * 64 + bb]        = ah;
            hn[(size_t)(1024 + j0 + jj) * 64 + bb] = al;
        }

        // ---- prefetch xproj for next step ----
        {
            int tn = (t + 1 < Tq) ? t + 1 : t;
#pragma unroll
            for (int g = 0; g < 4; g++) {
                xp[0][g] = g_xproj[((size_t)tn * Bq + b0) * G4 + j0 + jj0 + g * 1024];
                xp[1][g] = g_xproj[((size_t)tn * Bq + b1) * G4 + j0 + jj1 + g * 1024];
            }
        }

        nbar++; grid_sync(phase0 + nbar);
    }
}

// ---------------------------------------------------------------
extern "C" void kernel_launch(void* const* d_in, const int* in_sizes, int n_in,
                              void* d_out, int out_size) {
    const float* x    = (const float*)d_in[0];   // [B, T, I]
    const float* Wx   = (const float*)d_in[1];   // [I, 4H]
    const float* Wh   = (const float*)d_in[2];   // [H, 4H]
    const float* bias = (const float*)d_in[3];   // [4H]
    float* out = (float*)d_out;                  // [B, T, H]

    const int rec_smem = 131072 + 2 * 32768 + 32 * 65 * 4;   // ~205 KB
    cudaFuncSetAttribute(lstm_tc_kernel,
                         cudaFuncAttributeMaxDynamicSharedMemorySize, rec_smem);

    split_x_kernel<<<(Bq * Tq * Iq / 2) / 256, 256>>>(x);
    split_w_kernel<<<G4 / 256, 256>>>(Wx);
    gemm_xproj_mma<<<(Bq * Tq / 128) * (G4 / 128), 256>>>(bias);
    lstm_tc_kernel<<<NBLK, 256, rec_smem>>>(Wh, out);
}

// round 14
// speedup vs baseline: 1.0922x; 1.0922x over previous
#include <cuda_runtime.h>
#include <cuda_bf16.h>
#include <math.h>
#include <stdint.h>

#define Bq 64
#define Tq 512
#define Iq 1024
#define Hq 1024
#define G4 4096          // 4*H
#define KEXP 3072        // 3 * Iq (phase-1 split, interleaved)
#define KR2 2048         // 2 * Hq (phase-2 split, segmented [ah|al])
#define NBLK 128

// ---- scratch (static __device__; no allocations allowed) ----
__device__ float g_xproj[(size_t)Tq * Bq * G4];               // [t][b][4H]
__device__ unsigned g_Aexp[(size_t)(Bq * Tq) * (KEXP / 2)];   // bf16x2 [m][k']
__device__ unsigned g_Bexp[(size_t)G4 * (KEXP / 2)];          // bf16x2 [n][k']
__device__ __align__(128) __nv_bfloat16 g_hexp[2][(size_t)KR2 * Bq]; // h' [k'][64]

__device__ unsigned g_arrive  = 0;    // monotonic arrival counter (REDG target)
__device__ unsigned g_release = 0;    // monotonic release word

// =============== helpers ===============
__device__ __forceinline__ uint32_t smem_u32(const void* p) {
    uint32_t a;
    asm("{ .reg .u64 t; cvta.to.shared.u64 t, %1; cvt.u32.u64 %0, t; }"
        : "=r"(a) : "l"(p));
    return a;
}

#define CP_ASYNC16(dst, src) \
    asm volatile("cp.async.cg.shared.global [%0], [%1], 16;" :: "r"(dst), "l"(src))
#define CP_COMMIT() asm volatile("cp.async.commit_group;" ::: "memory")
#define CP_WAIT0()  asm volatile("cp.async.wait_group 0;" ::: "memory")
#define CP_WAIT1()  asm volatile("cp.async.wait_group 1;" ::: "memory")
#define CP_WAIT2()  asm volatile("cp.async.wait_group 2;" ::: "memory")

#define BAR_SYNC(id, n)   asm volatile("bar.sync %0, %1;"   :: "r"(id), "r"(n) : "memory")
#define BAR_ARRIVE(id, n) asm volatile("bar.arrive %0, %1;" :: "r"(id), "r"(n) : "memory")

#define LDMX4(r, addr) \
    asm volatile("ldmatrix.sync.aligned.m8n8.x4.shared.b16 {%0,%1,%2,%3}, [%4];" \
        : "=r"((r)[0]), "=r"((r)[1]), "=r"((r)[2]), "=r"((r)[3]) : "r"(addr))

#define LDMX4T(r, addr) \
    asm volatile("ldmatrix.sync.aligned.m8n8.x4.trans.shared.b16 {%0,%1,%2,%3}, [%4];" \
        : "=r"((r)[0]), "=r"((r)[1]), "=r"((r)[2]), "=r"((r)[3]) : "r"(addr))

#define MMA16816(c, a, b) \
    asm volatile("mma.sync.aligned.m16n8k16.row.col.f32.bf16.bf16.f32 " \
        "{%0,%1,%2,%3}, {%4,%5,%6,%7}, {%8,%9}, {%0,%1,%2,%3};" \
        : "+f"((c)[0]), "+f"((c)[1]), "+f"((c)[2]), "+f"((c)[3]) \
        : "r"((a)[0]), "r"((a)[1]), "r"((a)[2]), "r"((a)[3]), \
          "r"((b)[0]), "r"((b)[1]))

__device__ __forceinline__ void bf16_split(float v, unsigned& hi, unsigned& lo) {
    __nv_bfloat16 h = __float2bfloat16(v);
    float rem = v - __bfloat162float(h);
    __nv_bfloat16 l = __float2bfloat16(rem);
    hi = (unsigned)__bfloat16_as_ushort(h);
    lo = (unsigned)__bfloat16_as_ushort(l);
}

// =============== counter reset (per launch; keeps graph replays deterministic) ==
__global__ void reset_bar_kernel() {
    if (threadIdx.x == 0) { g_arrive = 0u; g_release = 0u; }
}

// =============== split / expand kernels (phase 1, unchanged) ===============
__global__ void split_x_kernel(const float* __restrict__ x) {
    size_t e2 = (size_t)blockIdx.x * 256 + threadIdx.x;
    float2 v = *(const float2*)(x + e2 * 2);
    size_t f0 = e2 * 2;
    size_t m = f0 >> 10;
    int k = (int)(f0 & 1023);
    unsigned h0, l0, h1, l1;
    bf16_split(v.x, h0, l0);
    bf16_split(v.y, h1, l1);
    unsigned* dst = g_Aexp + m * (KEXP / 2) + (size_t)(k >> 1) * 3;
    dst[0] = h0 | (h0 << 16);
    dst[1] = l0 | (h1 << 16);
    dst[2] = h1 | (l1 << 16);
}

__global__ void split_w_kernel(const float* __restrict__ Wx) {
    int n = blockIdx.x * 256 + threadIdx.x;
    unsigned* dst = g_Bexp + (size_t)n * (KEXP / 2);
#pragma unroll 4
    for (int k = 0; k < Iq; k += 2) {
        float w0 = Wx[(size_t)k * G4 + n];
        float w1 = Wx[(size_t)(k + 1) * G4 + n];
        unsigned h0, l0, h1, l1;
        bf16_split(w0, h0, l0);
        bf16_split(w1, h1, l1);
        unsigned* d = dst + (k >> 1) * 3;
        d[0] = h0 | (l0 << 16);
        d[1] = h0 | (h1 << 16);
        d[2] = l1 | (h1 << 16);
    }
}

// =============== Phase 1: mma.sync bf16 GEMM (unchanged from R5) ===============
__global__ void __launch_bounds__(256, 2)
gemm_xproj_mma(const float* __restrict__ bias) {
    __shared__ __align__(1024) unsigned char sm[2][16384];
    const uint32_t smbase = smem_u32(sm);

    const int tid  = threadIdx.x;
    const int wid  = tid >> 5;
    const int lane = tid & 31;
    const int wm   = wid & 1;
    const int wn   = wid >> 1;

    int bid = blockIdx.x;
    int gid = bid >> 9;
    int r = bid & 511;
    int mt = gid * 16 + (r & 15);
    int nt = r >> 4;
    const int m0 = mt * 128, n0 = nt * 128;

    const int gq = lane >> 3;
    const int rl = lane & 7;
    uint32_t a_addr[4], b_addr[2];
#pragma unroll
    for (int mf = 0; mf < 4; mf++) {
        int row = wm * 64 + mf * 16 + rl + (gq & 1) * 8;
        int q = (gq >> 1) ^ ((row >> 1) & 3);
        a_addr[mf] = smbase + row * 64 + q * 16;
    }
#pragma unroll
    for (int np = 0; np < 2; np++) {
        int row = wn * 32 + np * 16 + rl + (gq & 1) * 8;
        int q = (gq >> 1) ^ ((row >> 1) & 3);
        b_addr[np] = smbase + 8192 + row * 64 + q * 16;
    }

    const int4* A4 = (const int4*)g_Aexp;
    const int4* B4 = (const int4*)g_Bexp;
    auto load_chunk = [&](int c, int buf) {
        uint32_t sb = smbase + buf * 16384;
#pragma unroll
        for (int i = 0; i < 2; i++) {
            int u = tid + i * 256;
            int row = u >> 2, q = u & 3;
            uint32_t dst = sb + row * 64 + ((q ^ ((row >> 1) & 3)) << 4);
            CP_ASYNC16(dst, A4 + (size_t)(m0 + row) * 384 + c * 4 + q);
        }
#pragma unroll
        for (int i = 0; i < 2; i++) {
            int u = tid + i * 256;
            int row = u >> 2, q = u & 3;
            uint32_t dst = sb + 8192 + row * 64 + ((q ^ ((row >> 1) & 3)) << 4);
            CP_ASYNC16(dst, B4 + (size_t)(n0 + row) * 384 + c * 4 + q);
        }
    };

    float acc[4][4][4];
#pragma unroll
    for (int mf = 0; mf < 4; mf++)
#pragma unroll
        for (int nf = 0; nf < 4; nf++)
#pragma unroll
            for (int e = 0; e < 4; e++) acc[mf][nf][e] = 0.f;

    load_chunk(0, 0);
    CP_COMMIT();
    CP_WAIT0();
    __syncthreads();

    const int NCH = KEXP / 32;
    for (int c = 0; c < NCH; c++) {
        if (c + 1 < NCH) { load_chunk(c + 1, (c + 1) & 1); CP_COMMIT(); }

        const uint32_t boff = (c & 1) * 16384u;
#pragma unroll
        for (int kk = 0; kk < 2; kk++) {
            const uint32_t kx = kk << 5;
            uint32_t a[4][4], b[4][2];
#pragma unroll
            for (int mf = 0; mf < 4; mf++)
                LDMX4(a[mf], (a_addr[mf] + boff) ^ kx);
#pragma unroll
            for (int np = 0; np < 2; np++) {
                uint32_t rr[4];
                LDMX4(rr, (b_addr[np] + boff) ^ kx);
                b[np * 2][0] = rr[0]; b[np * 2][1] = rr[2];
                b[np * 2 + 1][0] = rr[1]; b[np * 2 + 1][1] = rr[3];
            }
#pragma unroll
            for (int mf = 0; mf < 4; mf++)
#pragma unroll
                for (int nf = 0; nf < 4; nf++)
                    MMA16816(acc[mf][nf], a[mf], b[nf]);
        }
        if (c + 1 < NCH) CP_WAIT0();
        __syncthreads();
    }

#pragma unroll
    for (int mf = 0; mf < 4; mf++) {
        int m = m0 + wm * 64 + mf * 16 + (lane >> 2);
#pragma unroll
        for (int nf = 0; nf < 4; nf++) {
            int n = n0 + wn * 32 + nf * 8 + (lane & 3) * 2;
            float2 bs = *(const float2*)&bias[n];
            {
                int b = m >> 9, t = m & 511;
                size_t idx = ((size_t)t * Bq + b) * G4 + n;
                float2 v = make_float2(acc[mf][nf][0] + bs.x, acc[mf][nf][1] + bs.y);
                *(float2*)&g_xproj[idx] = v;
            }
            {
                int m2 = m + 8;
                int b = m2 >> 9, t = m2 & 511;
                size_t idx = ((size_t)t * Bq + b) * G4 + n;
                float2 v = make_float2(acc[mf][nf][2] + bs.x, acc[mf][nf][3] + bs.y);
                *(float2*)&g_xproj[idx] = v;
            }
        }
    }
}

// =============== grid barrier v2 (FIXED): REDG arrivals + single poller ========
// Writer side:  st h' ; fence.sc ; red.add (arrival)
// Block 0:      poll arrive ; fence.sc ; st release      <-- fence was missing
// Waiters:      poll release ; fence.sc ; read h'
// This forms a valid causality chain in the PTX memory model.
__device__ __forceinline__ void grid_sync2(unsigned step) {
    __syncthreads();
    if (threadIdx.x == 0) {
        __threadfence();
        asm volatile("red.global.add.u32 [%0], %1;" :: "l"(&g_arrive), "r"(1u) : "memory");
        if (blockIdx.x == 0) {
            const unsigned tgt = step * (unsigned)gridDim.x;
            unsigned v;
            do {
                asm volatile("ld.global.cg.u32 %0, [%1];" : "=r"(v) : "l"(&g_arrive));
            } while (v < tgt);
            __threadfence();   // order observation of arrivals before release store
            asm volatile("st.global.cg.u32 [%0], %1;" :: "l"(&g_release), "r"(step) : "memory");
        } else {
            unsigned v;
            while (true) {
                asm volatile("ld.global.cg.u32 %0, [%1];" : "=r"(v) : "l"(&g_release));
                if (v >= step) break;
                __nanosleep(32);
            }
        }
        __threadfence();
    }
    __syncthreads();
}

// =============== Phase 2: tensor-core persistent recurrence (R11 + barrier fix) =
// 256 threads (warps 0-3 MMA, 4-7 producers), 8 chunks/step of 256 k'-rows
// (32KB), 3 SMEM buffers, 2-stage register pipelining.
// SMEM: BH @0 (64KB), BL @64KB (64KB), A bufs 3x32KB @128KB.  Total 224KB.
// Barriers: RDY 1-3, FREE 4-6 (count 256). Buffer of global chunk g = g%3.
#define LOAD_AH(p, kkv) do { \
    LDMX4T(aF[p], abase + (kkv) * 2048); \
    uint32_t cidx = ((kc0 + (kkv) * 2) | gqk) ^ bswz; \
    uint32_t rr[4]; \
    LDMX4(rr, Bsb + b_row_off[0] + (cidx << 4)); \
    bHF[p][0][0] = rr[0]; bHF[p][0][1] = rr[2]; \
    bHF[p][1][0] = rr[1]; bHF[p][1][1] = rr[3]; \
    LDMX4(rr, Bsb + b_row_off[1] + (cidx << 4)); \
    bHF[p][2][0] = rr[0]; bHF[p][2][1] = rr[2]; \
    bHF[p][3][0] = rr[1]; bHF[p][3][1] = rr[3]; \
    LDMX4(rr, Bsb + 65536u + b_row_off[0] + (cidx << 4)); \
    bLF[p][0][0] = rr[0]; bLF[p][0][1] = rr[2]; \
    bLF[p][1][0] = rr[1]; bLF[p][1][1] = rr[3]; \
    LDMX4(rr, Bsb + 65536u + b_row_off[1] + (cidx << 4)); \
    bLF[p][2][0] = rr[0]; bLF[p][2][1] = rr[2]; \
    bLF[p][3][0] = rr[1]; bLF[p][3][1] = rr[3]; \
} while (0)

#define LOAD_AL(p, kkv) do { \
    LDMX4T(aF[p], abase + (kkv) * 2048); \
    uint32_t cidx = ((kc0 + (kkv) * 2) | gqk) ^ bswz; \
    uint32_t rr[4]; \
    LDMX4(rr, Bsb + b_row_off[0] + (cidx << 4)); \
    bHF[p][0][0] = rr[0]; bHF[p][0][1] = rr[2]; \
    bHF[p][1][0] = rr[1]; bHF[p][1][1] = rr[3]; \
    LDMX4(rr, Bsb + b_row_off[1] + (cidx << 4)); \
    bHF[p][2][0] = rr[0]; bHF[p][2][1] = rr[2]; \
    bHF[p][3][0] = rr[1]; bHF[p][3][1] = rr[3]; \
} while (0)

__global__ void __launch_bounds__(256, 1)
lstm_tc_kernel(const float* __restrict__ Wh, float* __restrict__ out) {
    extern __shared__ __align__(128) char sm2[];
    const uint32_t Bsb = smem_u32(sm2);
    const uint32_t Asb = Bsb + 131072u;

    const int tid  = threadIdx.x;
    const int wid  = tid >> 5;
    const int lane = tid & 31;
    const int j0   = blockIdx.x * 8;
    const bool is_mma = (wid < 4);

    // ---- build split-Wh slices BH / BL (once) ----
    for (int idx = tid; idx < 32 * 1024; idx += 256) {
        int n = idx & 31;
        int k = idx >> 5;
        int g = n >> 3, jj = n & 7;
        float w = Wh[(size_t)k * G4 + g * 1024 + j0 + jj];
        unsigned bh, bl;
        bf16_split(w, bh, bl);
        uint32_t base = (uint32_t)(n * 2048 + (((k >> 3) ^ (n & 7)) << 4) + (k & 7) * 2);
        *(unsigned short*)(sm2 + base)          = (unsigned short)bh;
        *(unsigned short*)(sm2 + 65536u + base) = (unsigned short)bl;
    }

    // ---- zero my rows of h'[0] ----
    {
        __nv_bfloat16* hz = g_hexp[0];
        for (int idx = tid; idx < 16 * 64; idx += 256) {
            int r = idx >> 6;
            int row = (r < 8) ? (j0 + r) : (1024 + j0 + (r - 8));
            hz[(size_t)row * 64 + (idx & 63)] = __ushort_as_bfloat16(0);
        }
    }

    // ---- per-thread MMA constants ----
    const int gq = lane >> 3, rl = lane & 7;
    const uint32_t a_off = (uint32_t)((rl + ((gq >> 1) << 3)) * 128 +
                           ((wid * 32 + (gq & 1) * 16) ^ (rl << 4)));
    uint32_t b_row_off[2];
#pragma unroll
    for (int nh = 0; nh < 2; nh++)
        b_row_off[nh] = (uint32_t)((nh * 16 + rl + (gq & 1) * 8) * 2048);
    const uint32_t gqk = (uint32_t)(gq >> 1);
    const uint32_t bswz = (uint32_t)rl;

    float acc[4][4];
#pragma unroll
    for (int g = 0; g < 4; g++)
#pragma unroll
        for (int e = 0; e < 4; e++) acc[g][e] = 0.f;
    float cst[4] = {0.f, 0.f, 0.f, 0.f};

    const int pb0 = wid * 16 + (lane >> 2);
    const int pjj0 = (lane & 3) * 2;

    unsigned nbar = 0;
    nbar++; grid_sync2(nbar);     // BH/BL + h'[0] visible

    const int htid = tid - 128;

    // xproj prefetch regs (consumers)
    float2 xp[2][4];
    if (is_mma) {
#pragma unroll
        for (int hb = 0; hb < 2; hb++) {
            int b = pb0 + hb * 8;
            size_t base = (size_t)b * G4 + j0 + pjj0;
#pragma unroll
            for (int g = 0; g < 4; g++)
                xp[hb][g] = *(const float2*)&g_xproj[base + g * 1024];
        }
    }

    for (int t = 0; t < Tq; t++) {
        if (!is_mma) {
            // ================= producer (warps 4-7) =================
            const __nv_bfloat16* Asrc = g_hexp[t & 1];
            for (int ch = 0; ch < 8; ch++) {
                unsigned gch = (unsigned)t * 8u + (unsigned)ch;
                int gb = (int)(gch % 3u);
                if (gch >= 3u) BAR_SYNC(4 + gb, 256);
                uint32_t sbuf = Asb + (uint32_t)gb * 32768u;
                const __nv_bfloat16* src = Asrc + (size_t)ch * 16384;
#pragma unroll
                for (int i = 0; i < 16; i++) {
                    int u = htid + i * 128;
                    int krow = u >> 3, q = u & 7;
                    uint32_t dst = sbuf + krow * 128 + (((uint32_t)q ^ (krow & 7)) << 4);
                    CP_ASYNC16(dst, src + (size_t)krow * 64 + q * 8);
                }
                CP_COMMIT();
                if (ch >= 2) { CP_WAIT2(); BAR_ARRIVE(1 + (int)((gch - 2u) % 3u), 256); }
            }
            CP_WAIT1(); BAR_ARRIVE(1 + (int)(((unsigned)t * 8u + 6u) % 3u), 256);
            CP_WAIT0(); BAR_ARRIVE(1 + (int)(((unsigned)t * 8u + 7u) % 3u), 256);
        } else {
            // ================= consumer (warps 0-3) =================
            for (int ch = 0; ch < 8; ch++) {
                unsigned gch = (unsigned)t * 8u + (unsigned)ch;
                int gb = (int)(gch % 3u);
                BAR_SYNC(1 + gb, 256);
                const uint32_t abase = Asb + (uint32_t)gb * 32768u + a_off;
                const uint32_t kc0 = (uint32_t)((ch & 3) * 32);
                if (ch < 4) {
                    // ah chunk: vs BH and BL, 2-stage pipelined
                    uint32_t aF[2][4], bHF[2][4][2], bLF[2][4][2];
                    LOAD_AH(0, 0);
#pragma unroll
                    for (int kk = 0; kk < 16; kk++) {
                        int cur = kk & 1;
                        if (kk < 15) {
                            int nxt = cur ^ 1;
                            LOAD_AH(nxt, kk + 1);
                        }
#pragma unroll
                        for (int g = 0; g < 4; g++) MMA16816(acc[g], aF[cur], bHF[cur][g]);
#pragma unroll
                        for (int g = 0; g < 4; g++) MMA16816(acc[g], aF[cur], bLF[cur][g]);
                    }
                } else {
                    // al chunk: vs BH only, 2-stage pipelined
                    uint32_t aF[2][4], bHF[2][4][2];
                    LOAD_AL(0, 0);
#pragma unroll
                    for (int kk = 0; kk < 16; kk++) {
                        int cur = kk & 1;
                        if (kk < 15) {
                            int nxt = cur ^ 1;
                            LOAD_AL(nxt, kk + 1);
                        }
#pragma unroll
                        for (int g = 0; g < 4; g++) MMA16816(acc[g], aF[cur], bHF[cur][g]);
                    }
                }
                BAR_ARRIVE(4 + gb, 256);
            }

            // ---- pointwise: gates -> c,h; write out + h' ----
            __nv_bfloat16* hn = g_hexp[(t + 1) & 1];
#pragma unroll
            for (int ci = 0; ci < 4; ci++) {
                int hb = ci >> 1;
                int b  = pb0 + hb * 8;
                int jj = pjj0 + (ci & 1);
                float ig = acc[0][ci] + ((ci & 1) ? xp[hb][0].y : xp[hb][0].x);
                float fg = acc[1][ci] + ((ci & 1) ? xp[hb][1].y : xp[hb][1].x);
                float gg = acc[2][ci] + ((ci & 1) ? xp[hb][2].y : xp[hb][2].x);
                float og = acc[3][ci] + ((ci & 1) ? xp[hb][3].y : xp[hb][3].x);

                float iv = 1.f / (1.f + __expf(-ig));
                float fv = 1.f / (1.f + __expf(-fg));
                float gv = tanhf(gg);
                float ov = 1.f / (1.f + __expf(-og));

                float c = fv * cst[ci] + iv * gv;
                float h = ov * tanhf(c);
                cst[ci] = c;

                out[((size_t)b * Tq + t) * Hq + j0 + jj] = h;

                __nv_bfloat16 ah = __float2bfloat16(h);
                float rem = h - __bfloat162float(ah);
                __nv_bfloat16 al = __float2bfloat16(rem);
                hn[(size_t)(j0 + jj) * 64 + b]        = ah;
                hn[(size_t)(1024 + j0 + jj) * 64 + b] = al;

                acc[0][ci] = 0.f; acc[1][ci] = 0.f;
                acc[2][ci] = 0.f; acc[3][ci] = 0.f;
            }

            // ---- prefetch xproj for next step ----
            {
                int tn = (t + 1 < Tq) ? t + 1 : t;
#pragma unroll
                for (int hb = 0; hb < 2; hb++) {
                    int b = pb0 + hb * 8;
                    size_t base = ((size_t)tn * Bq + b) * G4 + j0 + pjj0;
#pragma unroll
                    for (int g = 0; g < 4; g++)
                        xp[hb][g] = *(const float2*)&g_xproj[base + g * 1024];
                }
            }
        }

        nbar++; grid_sync2(nbar);
    }
}

// ---------------------------------------------------------------
extern "C" void kernel_launch(void* const* d_in, const int* in_sizes, int n_in,
                              void* d_out, int out_size) {
    const float* x    = (const float*)d_in[0];   // [B, T, I]
    const float* Wx   = (const float*)d_in[1];   // [I, 4H]
    const float* Wh   = (const float*)d_in[2];   // [H, 4H]
    const float* bias = (const float*)d_in[3];   // [4H]
    float* out = (float*)d_out;                  // [B, T, H]

    const int rec_smem = 131072 + 3 * 32768;     // 224 KB
    cudaFuncSetAttribute(lstm_tc_kernel,
                         cudaFuncAttributeMaxDynamicSharedMemorySize, rec_smem);

    reset_bar_kernel<<<1, 32>>>();
    split_x_kernel<<<(Bq * Tq * Iq / 2) / 256, 256>>>(x);
    split_w_kernel<<<G4 / 256, 256>>>(Wx);
    gemm_xproj_mma<<<(Bq * Tq / 128) * (G4 / 128), 256>>>(bias);
    lstm_tc_kernel<<<NBLK, 256, rec_smem>>>(Wh, out);
}